// round 4
// baseline (speedup 1.0000x reference)
#include <cuda_runtime.h>
#include <cfloat>

#define SPATIAL_SCALE 0.0625f
#define CC 256
#define HH 64
#define WW 64
#define KK 128
#define PH 7
#define PW 7
#define WARPS_PER_BLOCK 8

__global__ __launch_bounds__(256) void roipool_warp_kernel(
        const float* __restrict__ x,
        const float* __restrict__ rois,
        float* __restrict__ out) {
    __shared__ float colmax[WARPS_PER_BLOCK][PH * WW];  // [warp][ph*64 + w]

    const int warpLocal  = threadIdx.x >> 5;
    const int lane       = threadIdx.x & 31;
    const int warpGlobal = blockIdx.x * WARPS_PER_BLOCK + warpLocal;
    if (warpGlobal >= KK * CC) return;

    const int k = warpGlobal >> 8;   // / CC
    const int c = warpGlobal & 255;  // % CC

    // ---- ROI geometry (identical math to the bit-exact passing kernel) ----
    const float* r = rois + k * 5;
    const int b  = (int)__ldg(&r[0]);
    const int x1 = (int)rintf(__ldg(&r[1]) * SPATIAL_SCALE);
    const int y1 = (int)rintf(__ldg(&r[2]) * SPATIAL_SCALE);
    const int x2 = (int)rintf(__ldg(&r[3]) * SPATIAL_SCALE);
    const int y2 = (int)rintf(__ldg(&r[4]) * SPATIAL_SCALE);

    const int roi_w = max(x2 - x1 + 1, 1);
    const int roi_h = max(y2 - y1 + 1, 1);

    const float INV7 = __uint_as_float(0x3E124925u);  // fl(1/7), matches XLA recip-mul
    const float bw = __fmul_rn((float)roi_w, INV7);
    const float bh = __fmul_rn((float)roi_h, INV7);

    // Per-bin row bounds (constant-indexed via unroll -> registers)
    int hs[PH], he[PH];
#pragma unroll
    for (int ph = 0; ph < PH; ++ph) {
        int s = (int)floorf(__fmul_rn((float)ph, bh)) + y1;
        int e = (int)ceilf(__fmul_rn((float)(ph + 1), bh)) + y1;
        hs[ph] = min(max(s, 0), HH);
        he[ph] = min(max(e, 0), HH);
    }

    // Column window = union of all pw bins = [ws(0), we(6)) clipped
    const int wload_s = min(max(x1, 0), WW);
    const int we6 = (int)ceilf(__fmul_rn((float)PW, bw)) + x1;
    const int wload_e = min(max(we6, 0), WW);

    const float* plane = x + ((long)b * CC + c) * (HH * WW);
    float* my = colmax[warpLocal];

    // ---- Load phase: coalesced row loads, per-column max into smem ----
    for (int wbase = wload_s; wbase < wload_e; wbase += 32) {
        const int w = wbase + lane;
        const bool valid = (w < wload_e);
#pragma unroll
        for (int ph = 0; ph < PH; ++ph) {
            float cm = -FLT_MAX;
            const int h0 = hs[ph], h1 = he[ph];
            if (valid) {
                for (int h = h0; h < h1; ++h) {
                    cm = fmaxf(cm, __ldg(&plane[h * WW + w]));
                }
                my[ph * WW + w] = cm;
            }
        }
    }
    __syncwarp();

    // ---- Reduce phase: 49 outputs per warp (lanes take t and t+32) ----
    float* obase = out + (long)warpGlobal * (PH * PW);
    for (int t = lane; t < PH * PW; t += 32) {
        const int ph = t / PW;
        const int pw = t - ph * PW;

        int ws = (int)floorf(__fmul_rn((float)pw, bw)) + x1;
        int we = (int)ceilf(__fmul_rn((float)(pw + 1), bw)) + x1;
        ws = min(max(ws, 0), WW);
        we = min(max(we, 0), WW);

        float m;
        if (hs[ph] >= he[ph] || ws >= we) {
            m = 0.0f;
        } else {
            m = -FLT_MAX;
            for (int w = ws; w < we; ++w) {
                m = fmaxf(m, my[ph * WW + w]);
            }
        }
        obase[t] = m;
    }
}

extern "C" void kernel_launch(void* const* d_in, const int* in_sizes, int n_in,
                              void* d_out, int out_size) {
    const float* x    = (const float*)d_in[0];
    const float* rois = (const float*)d_in[1];
    if (n_in >= 2 && in_sizes[0] == KK * 5) {
        x    = (const float*)d_in[1];
        rois = (const float*)d_in[0];
    }
    float* out = (float*)d_out;
    const int totalWarps = KK * CC;                      // 32768
    const int blocks = totalWarps / WARPS_PER_BLOCK;     // 4096
    roipool_warp_kernel<<<blocks, 256>>>(x, rois, out);
}

// round 5
// speedup vs baseline: 1.3697x; 1.3697x over previous
#include <cuda_runtime.h>
#include <cfloat>

#define SPATIAL_SCALE 0.0625f
#define CC 256
#define HH 64
#define WW 64
#define HW 4096
#define KK 128
#define PH 7
#define PW 7
#define NBIN 49          // PH*PW
#define RES_PITCH 33     // bank-conflict-free pitch for [bin][lane]

// 8MB NHWC scratch: xt[b][h][w][c]
__device__ float g_xt[2 * HW * CC];

// ---------------- Kernel A: NCHW -> NHWC transpose ----------------
__global__ __launch_bounds__(256) void transpose_kernel(const float* __restrict__ x) {
    __shared__ float tile[32][33];
    const int b   = blockIdx.z;
    const int hw0 = blockIdx.x * 32;
    const int c0  = blockIdx.y * 32;
    const int tx  = threadIdx.x;   // 0..31
    const int ty  = threadIdx.y;   // 0..7

    const float* src = x + ((long)b * CC + c0) * HW + hw0;
#pragma unroll
    for (int j = 0; j < 4; ++j) {
        int cc = ty + j * 8;
        tile[cc][tx] = src[(long)cc * HW + tx];
    }
    __syncthreads();
    float* dst = g_xt + ((long)b * HW + hw0) * CC + c0;
#pragma unroll
    for (int j = 0; j < 4; ++j) {
        int hh = ty + j * 8;
        dst[(long)hh * CC + tx] = tile[tx][hh];
    }
}

// ---------------- Kernel B: pooled max, coalesced in channels ----------------
__global__ __launch_bounds__(256) void roipool_nhwc_kernel(
        const float* __restrict__ rois,
        float* __restrict__ out) {
    __shared__ float res[NBIN * RES_PITCH];

    const int k    = blockIdx.x >> 3;        // 128 rois
    const int c0   = (blockIdx.x & 7) << 5;  // 8 chunks of 32 channels
    const int lane = threadIdx.x & 31;

    // ---- ROI geometry (bit-exact math, verbatim from passing kernel) ----
    const float* r = rois + k * 5;
    const int b  = (int)__ldg(&r[0]);
    const int x1 = (int)rintf(__ldg(&r[1]) * SPATIAL_SCALE);
    const int y1 = (int)rintf(__ldg(&r[2]) * SPATIAL_SCALE);
    const int x2 = (int)rintf(__ldg(&r[3]) * SPATIAL_SCALE);
    const int y2 = (int)rintf(__ldg(&r[4]) * SPATIAL_SCALE);

    const int roi_w = max(x2 - x1 + 1, 1);
    const int roi_h = max(y2 - y1 + 1, 1);

    const float INV7 = __uint_as_float(0x3E124925u);  // fl(1/7): XLA recip-mul
    const float bw = __fmul_rn((float)roi_w, INV7);
    const float bh = __fmul_rn((float)roi_h, INV7);

    // Per-thread channel pointer: xt[b][.][.][c0+lane]
    const float* chan = g_xt + (long)b * HW * CC + c0 + lane;

    // 1568 work items = 49 bins x 32 channels; warp-aligned so each warp
    // iteration handles ONE bin across 32 consecutive channels.
#pragma unroll
    for (int i = 0; i < 7; ++i) {
        const int item = threadIdx.x + (i << 8);
        if (item < NBIN * 32) {
            const int bin = item >> 5;           // uniform across warp
            const int ph  = bin / PW;
            const int pw  = bin - ph * PW;

            int hs = (int)floorf(__fmul_rn((float)ph, bh)) + y1;
            int he = (int)ceilf(__fmul_rn((float)(ph + 1), bh)) + y1;
            int ws = (int)floorf(__fmul_rn((float)pw, bw)) + x1;
            int we = (int)ceilf(__fmul_rn((float)(pw + 1), bw)) + x1;
            hs = min(max(hs, 0), HH);
            he = min(max(he, 0), HH);
            ws = min(max(ws, 0), WW);
            we = min(max(we, 0), WW);

            float m;
            if (hs >= he || ws >= we) {
                m = 0.0f;
            } else {
                m = -FLT_MAX;
                for (int h = hs; h < he; ++h) {
                    const float* rowp = chan + ((h << 6) + ws) * CC;
#pragma unroll 4
                    for (int w = 0; w < we - ws; ++w) {
                        m = fmaxf(m, __ldg(rowp + w * CC));
                    }
                }
            }
            res[bin * RES_PITCH + lane] = m;
        }
    }
    __syncthreads();

    // Contiguous coalesced store: block owns out[(k*256+c0) .. +1568)
    float* ob = out + ((long)k * CC + c0) * NBIN;
    for (int j = threadIdx.x; j < NBIN * 32; j += 256) {
        const int cl  = j / NBIN;
        const int bin = j - cl * NBIN;
        ob[j] = res[bin * RES_PITCH + cl];
    }
}

extern "C" void kernel_launch(void* const* d_in, const int* in_sizes, int n_in,
                              void* d_out, int out_size) {
    const float* x    = (const float*)d_in[0];
    const float* rois = (const float*)d_in[1];
    if (n_in >= 2 && in_sizes[0] == KK * 5) {
        x    = (const float*)d_in[1];
        rois = (const float*)d_in[0];
    }
    float* out = (float*)d_out;

    dim3 gA(HW / 32, CC / 32, 2);     // 128 x 8 x 2 = 2048 blocks
    dim3 bA(32, 8);
    transpose_kernel<<<gA, bA>>>(x);

    roipool_nhwc_kernel<<<KK * 8, 256>>>(rois, out);  // 1024 blocks
}

// round 7
// speedup vs baseline: 2.0595x; 1.5036x over previous
#include <cuda_runtime.h>
#include <cfloat>

#define SPATIAL_SCALE 0.0625f
#define CC 256
#define HH 64
#define WW 64
#define HW 4096
#define KK 128
#define PH 7
#define PW 7
#define NBIN 49

// 8MB NHWC scratch: xt[b][h][w][c], float4-aligned
__device__ __align__(16) float g_xt[2 * HW * CC];

// ---------------- Kernel A: NCHW -> NHWC transpose (float4 both sides) ----------------
// Tile: 32 channels x 128 hw. Grid (HW/128, CC/32, 2), block 256.
__global__ __launch_bounds__(256) void transpose_kernel(const float* __restrict__ x) {
    __shared__ float tile[32][132];   // [c][hw], padded
    const int b   = blockIdx.z;
    const int hw0 = blockIdx.x * 128;
    const int c0  = blockIdx.y * 32;
    const int tid = threadIdx.x;

    // Load: 4 float4s per thread along hw (coalesced 512B/warp)
    const int hw4 = tid & 31;        // which 16B quad in the 128-hw row
    const int cL  = tid >> 5;        // 0..7
#pragma unroll
    for (int j = 0; j < 4; ++j) {
        const int c = cL + j * 8;
        const float4 v = *reinterpret_cast<const float4*>(
            x + ((long)(b * CC + c0 + c)) * HW + hw0 + hw4 * 4);
        tile[c][hw4 * 4 + 0] = v.x;
        tile[c][hw4 * 4 + 1] = v.y;
        tile[c][hw4 * 4 + 2] = v.z;
        tile[c][hw4 * 4 + 3] = v.w;
    }
    __syncthreads();

    // Store: 4 float4s per thread along c (coalesced)
    const int cq = tid & 7;          // which c-quad (8 quads = 32 c)
    const int h0 = tid >> 3;         // 0..31
#pragma unroll
    for (int j = 0; j < 4; ++j) {
        const int hh = h0 + j * 32;
        float4 v;
        v.x = tile[cq * 4 + 0][hh];
        v.y = tile[cq * 4 + 1][hh];
        v.z = tile[cq * 4 + 2][hh];
        v.w = tile[cq * 4 + 3][hh];
        *reinterpret_cast<float4*>(
            g_xt + ((long)(b * HW + hw0 + hh)) * CC + c0 + cq * 4) = v;
    }
}

// ---------------- Kernel B: pool. Block = (k, c-chunk32, ph). 224 threads. ----------------
// Warp = one (ph,pw) bin across 32 consecutive channels -> 128B coalesced gathers.
__global__ __launch_bounds__(224) void roipool_kernel(
        const float* __restrict__ rois,
        float* __restrict__ out) {
    __shared__ float res[32 * 9 + 4];   // [c-local][pw], pitch 9 (coprime with 32)

    const int bx  = blockIdx.x;
    const int k   = bx / 56;
    const int rem = bx - k * 56;
    const int c0  = (rem / 7) << 5;
    const int ph  = rem % 7;

    const int t    = threadIdx.x;   // 0..223
    const int pw   = t >> 5;        // 0..6, uniform per warp
    const int cl   = t & 31;

    // ---- ROI geometry (bit-exact, verbatim) ----
    const float* r = rois + k * 5;
    const int b  = (int)__ldg(&r[0]);
    const int x1 = (int)rintf(__ldg(&r[1]) * SPATIAL_SCALE);
    const int y1 = (int)rintf(__ldg(&r[2]) * SPATIAL_SCALE);
    const int x2 = (int)rintf(__ldg(&r[3]) * SPATIAL_SCALE);
    const int y2 = (int)rintf(__ldg(&r[4]) * SPATIAL_SCALE);

    const int roi_w = max(x2 - x1 + 1, 1);
    const int roi_h = max(y2 - y1 + 1, 1);

    const float INV7 = __uint_as_float(0x3E124925u);  // fl(1/7): XLA recip-mul
    const float bw = __fmul_rn((float)roi_w, INV7);
    const float bh = __fmul_rn((float)roi_h, INV7);

    int hs = (int)floorf(__fmul_rn((float)ph, bh)) + y1;
    int he = (int)ceilf(__fmul_rn((float)(ph + 1), bh)) + y1;
    int ws = (int)floorf(__fmul_rn((float)pw, bw)) + x1;
    int we = (int)ceilf(__fmul_rn((float)(pw + 1), bw)) + x1;
    hs = min(max(hs, 0), HH);
    he = min(max(he, 0), HH);
    ws = min(max(ws, 0), WW);
    we = min(max(we, 0), WW);

    float m;
    if (hs >= he || ws >= we) {
        m = 0.0f;
    } else {
        float m0 = -FLT_MAX, m1 = -FLT_MAX;
        const int n = we - ws;
        const float* base = g_xt + ((long)b * HW) * CC + c0 + cl;
        for (int h = hs; h < he; ++h) {
            const float* p = base + ((h << 6) + ws) * CC;
            int w = 0;
            for (; w + 1 < n; w += 2) {
                m0 = fmaxf(m0, __ldg(p + (long)w * CC));
                m1 = fmaxf(m1, __ldg(p + (long)(w + 1) * CC));
            }
            if (w < n) m0 = fmaxf(m0, __ldg(p + (long)w * CC));
        }
        m = fmaxf(m0, m1);  // max is exact: reordering is bit-safe
    }
    res[cl * 9 + pw] = m;
    __syncthreads();

    // Store: block owns, per channel, 7 consecutive floats at out[(k*256+c)*49 + ph*7 .. +7)
    const int cl2 = t / 7;          // 0..31 (224 = 32*7)
    const int pw2 = t - cl2 * 7;
    out[((long)(k * CC + c0 + cl2)) * NBIN + ph * PW + pw2] = res[cl2 * 9 + pw2];
}

extern "C" void kernel_launch(void* const* d_in, const int* in_sizes, int n_in,
                              void* d_out, int out_size) {
    const float* x    = (const float*)d_in[0];
    const float* rois = (const float*)d_in[1];
    if (n_in >= 2 && in_sizes[0] == KK * 5) {
        x    = (const float*)d_in[1];
        rois = (const float*)d_in[0];
    }
    float* out = (float*)d_out;

    dim3 gA(HW / 128, CC / 32, 2);   // 32 x 8 x 2 = 512 blocks
    transpose_kernel<<<gA, 256>>>(x);

    roipool_kernel<<<KK * 8 * PH, 224>>>(rois, out);  // 7168 blocks
}

// round 8
// speedup vs baseline: 2.5580x; 1.2420x over previous
#include <cuda_runtime.h>
#include <cfloat>

#define SPATIAL_SCALE 0.0625f
#define CC 256
#define HH 64
#define WW 64
#define HW 4096
#define KK 128
#define PH 7
#define PW 7
#define NBIN 49

// 8MB NHWC scratch: xt[b][h][w][c], float4-aligned
__device__ __align__(16) float g_xt[2 * HW * CC];

// ---------------- Kernel A: NCHW -> NHWC transpose (float4 both sides) ----------------
__global__ __launch_bounds__(256) void transpose_kernel(const float* __restrict__ x) {
    __shared__ float tile[32][132];
    const int b   = blockIdx.z;
    const int hw0 = blockIdx.x * 128;
    const int c0  = blockIdx.y * 32;
    const int tid = threadIdx.x;

    const int hw4 = tid & 31;
    const int cL  = tid >> 5;
#pragma unroll
    for (int j = 0; j < 4; ++j) {
        const int c = cL + j * 8;
        const float4 v = *reinterpret_cast<const float4*>(
            x + ((long)(b * CC + c0 + c)) * HW + hw0 + hw4 * 4);
        tile[c][hw4 * 4 + 0] = v.x;
        tile[c][hw4 * 4 + 1] = v.y;
        tile[c][hw4 * 4 + 2] = v.z;
        tile[c][hw4 * 4 + 3] = v.w;
    }
    __syncthreads();

    const int cq = tid & 7;
    const int h0 = tid >> 3;
#pragma unroll
    for (int j = 0; j < 4; ++j) {
        const int hh = h0 + j * 32;
        float4 v;
        v.x = tile[cq * 4 + 0][hh];
        v.y = tile[cq * 4 + 1][hh];
        v.z = tile[cq * 4 + 2][hh];
        v.w = tile[cq * 4 + 3][hh];
        *reinterpret_cast<float4*>(
            g_xt + ((long)(b * HW + hw0 + hh)) * CC + c0 + cq * 4) = v;
    }
}

__device__ __forceinline__ float4 f4max(float4 a, float4 b) {
    a.x = fmaxf(a.x, b.x);
    a.y = fmaxf(a.y, b.y);
    a.z = fmaxf(a.z, b.z);
    a.w = fmaxf(a.w, b.w);
    return a;
}

// ---------------- Kernel B: pool. Block = (k, c-chunk128, ph). 224 threads. ----------------
// Warp = one (ph,pw) bin across 128 consecutive channels via LDG.128.
__global__ __launch_bounds__(224) void roipool_kernel(
        const float* __restrict__ rois,
        float* __restrict__ out) {
    __shared__ float res[128 * 8];      // [c-local][pw], pitch 8

    const int bx  = blockIdx.x;
    const int k   = bx / 14;            // 128 rois
    const int rem = bx - k * 14;
    const int c0  = (rem / 7) << 7;     // 0 or 128
    const int ph  = rem % 7;

    const int t    = threadIdx.x;       // 0..223
    const int pw   = t >> 5;            // warp-uniform
    const int cq   = t & 31;            // channel quad

    // ---- ROI geometry (bit-exact, verbatim) ----
    const float* r = rois + k * 5;
    const int b  = (int)__ldg(&r[0]);
    const int x1 = (int)rintf(__ldg(&r[1]) * SPATIAL_SCALE);
    const int y1 = (int)rintf(__ldg(&r[2]) * SPATIAL_SCALE);
    const int x2 = (int)rintf(__ldg(&r[3]) * SPATIAL_SCALE);
    const int y2 = (int)rintf(__ldg(&r[4]) * SPATIAL_SCALE);

    const int roi_w = max(x2 - x1 + 1, 1);
    const int roi_h = max(y2 - y1 + 1, 1);

    const float INV7 = __uint_as_float(0x3E124925u);  // fl(1/7): XLA recip-mul
    const float bw = __fmul_rn((float)roi_w, INV7);
    const float bh = __fmul_rn((float)roi_h, INV7);

    int hs = (int)floorf(__fmul_rn((float)ph, bh)) + y1;
    int he = (int)ceilf(__fmul_rn((float)(ph + 1), bh)) + y1;
    int ws = (int)floorf(__fmul_rn((float)pw, bw)) + x1;
    int we = (int)ceilf(__fmul_rn((float)(pw + 1), bw)) + x1;
    hs = min(max(hs, 0), HH);
    he = min(max(he, 0), HH);
    ws = min(max(ws, 0), WW);
    we = min(max(we, 0), WW);

    float4 m;
    if (hs >= he || ws >= we) {
        m = make_float4(0.f, 0.f, 0.f, 0.f);
    } else {
        float4 m0 = make_float4(-FLT_MAX, -FLT_MAX, -FLT_MAX, -FLT_MAX);
        float4 m1 = m0;
        const int n = we - ws;
        const float* base = g_xt + (long)b * HW * CC + c0 + cq * 4;
        for (int h = hs; h < he; ++h) {
            const float* p = base + (long)((h << 6) + ws) * CC;
            int w = 0;
            for (; w + 1 < n; w += 2) {
                m0 = f4max(m0, *reinterpret_cast<const float4*>(p + (long)w * CC));
                m1 = f4max(m1, *reinterpret_cast<const float4*>(p + (long)(w + 1) * CC));
            }
            if (w < n)
                m0 = f4max(m0, *reinterpret_cast<const float4*>(p + (long)w * CC));
        }
        m = f4max(m0, m1);   // max reordering is exact
    }
    res[(cq * 4 + 0) * 8 + pw] = m.x;
    res[(cq * 4 + 1) * 8 + pw] = m.y;
    res[(cq * 4 + 2) * 8 + pw] = m.z;
    res[(cq * 4 + 3) * 8 + pw] = m.w;
    __syncthreads();

    // Store: block owns out[(k*256+c0+c)*49 + ph*7 + p] for c in [0,128), p in [0,7)
    float* ob = out + ((long)(k * CC + c0)) * NBIN + ph * PW;
#pragma unroll
    for (int i = 0; i < 4; ++i) {
        const int j = t + i * 224;      // 0..895
        const int c = j / 7;
        const int p = j - c * 7;
        ob[(long)c * NBIN + p] = res[c * 8 + p];
    }
}

extern "C" void kernel_launch(void* const* d_in, const int* in_sizes, int n_in,
                              void* d_out, int out_size) {
    const float* x    = (const float*)d_in[0];
    const float* rois = (const float*)d_in[1];
    if (n_in >= 2 && in_sizes[0] == KK * 5) {
        x    = (const float*)d_in[1];
        rois = (const float*)d_in[0];
    }
    float* out = (float*)d_out;

    dim3 gA(HW / 128, CC / 32, 2);   // 512 blocks
    transpose_kernel<<<gA, 256>>>(x);

    roipool_kernel<<<KK * 2 * PH, 224>>>(rois, out);  // 1792 blocks
}